// round 2
// baseline (speedup 1.0000x reference)
#include <cuda_runtime.h>

typedef unsigned long long ULL;

__device__ __forceinline__ ULL pk2(float lo, float hi){
  ULL r; asm("mov.b64 %0, {%1,%2};" : "=l"(r) : "f"(lo), "f"(hi)); return r;
}
__device__ __forceinline__ float2 upk(ULL v){
  float2 r; asm("mov.b64 {%0,%1}, %2;" : "=f"(r.x), "=f"(r.y) : "l"(v)); return r;
}
#define FMA2(d,a,bb,c) asm("fma.rn.f32x2 %0, %1, %2, %3;" : "=l"(d) : "l"(a), "l"(bb), "l"(c))
#define MUL2(d,a,bb)   asm("mul.rn.f32x2 %0, %1, %2;"     : "=l"(d) : "l"(a), "l"(bb))

constexpr int NX_ = 128, NY_ = 128, NT_ = 64;
constexpr float EPS_ = 1e-5f;

// shared memory layout (floats)
constexpr int OFF_H   = 0;                 // h[64][128]
constexpr int OFF_QKV = 64*128;            // qkv[192][128]
constexpr int OFF_ATT = OFF_QKV + 192*128; // att[128][130] / ff-hidden[128][128] / scratch
constexpr int SMEM_FLOATS = OFF_ATT + 128*130;   // 49408 floats = 197632 bytes

// C[o][s] = act( sum_k A[k][s] * W[o*K+k] + Bv[o] ), token dim vectorized by f32x2
template<int OUT, int K, bool RELU>
__device__ __forceinline__ void gemm_tok(const float* __restrict__ A,
                                         const float* __restrict__ W,
                                         const float* __restrict__ Bv,
                                         float* __restrict__ C, int tid)
{
  constexpr int TO = OUT/16;
  const int tx = tid & 15;      // token tile: tokens 8*tx .. 8*tx+7
  const int ty = tid >> 4;      // outputs ty*TO + j
  const int tok = 8*tx;
  ULL acc[TO][4];
#pragma unroll
  for (int j=0;j<TO;j++){
    float b = __ldg(Bv + ty*TO + j);
    ULL bb = pk2(b,b);
#pragma unroll
    for (int p=0;p<4;p++) acc[j][p] = bb;
  }
#pragma unroll 2
  for (int k=0;k<K;k+=2){
    ULL a0[4], a1[4];
#pragma unroll
    for (int p=0;p<4;p++){
      a0[p] = *reinterpret_cast<const ULL*>(A + k*128     + tok + 2*p);
      a1[p] = *reinterpret_cast<const ULL*>(A + (k+1)*128 + tok + 2*p);
    }
#pragma unroll
    for (int j=0;j<TO;j++){
      float2 w2 = __ldg(reinterpret_cast<const float2*>(W + (ty*TO+j)*K + k));
      ULL w0 = pk2(w2.x, w2.x);
      ULL w1 = pk2(w2.y, w2.y);
#pragma unroll
      for (int p=0;p<4;p++){
        FMA2(acc[j][p], a0[p], w0, acc[j][p]);
        FMA2(acc[j][p], a1[p], w1, acc[j][p]);
      }
    }
  }
#pragma unroll
  for (int j=0;j<TO;j++){
#pragma unroll
    for (int p=0;p<4;p++){
      float2 v = upk(acc[j][p]);
      if (RELU){ v.x = fmaxf(v.x,0.f); v.y = fmaxf(v.y,0.f); }
      *reinterpret_cast<float2*>(C + (ty*TO+j)*128 + tok + 2*p) = v;
    }
  }
}

// h[d][s] = LN_d( h[d][s] + r[d][s] ) * gs[d] + gb[d]
__device__ __forceinline__ void add_ln(float* __restrict__ h,
                                       const float* __restrict__ r,
                                       const float* __restrict__ gs,
                                       const float* __restrict__ gb, int tid)
{
  if (tid < 128){
    const int s = tid;
    float sum=0.f, sq=0.f;
#pragma unroll 8
    for (int d=0; d<64; d++){
      float x = h[d*128+s] + r[d*128+s];
      sum += x; sq += x*x;
    }
    float m = sum * (1.f/64.f);
    float var = sq * (1.f/64.f) - m*m;
    float inv = rsqrtf(var + EPS_);
#pragma unroll 8
    for (int d=0; d<64; d++){
      float x = h[d*128+s] + r[d*128+s];
      h[d*128+s] = (x - m)*inv*__ldg(gs+d) + __ldg(gb+d);
    }
  }
}

__device__ __forceinline__ float dper(float diff, float L){
  float m = fmodf(diff + 0.5f*L, L);
  if (m < 0.f) m += L;
  return m - 0.5f*L;
}

__global__ void __launch_bounds__(256, 1)
ff_kernel(const int* __restrict__ q_lin_idx, const int* __restrict__ offs,
          const float* __restrict__ coords, const float* __restrict__ vals,
          const float* __restrict__ lg,
          const float* __restrict__ pw, const float* __restrict__ pb,
          const float* __restrict__ qw, const float* __restrict__ qbias,
          const float* __restrict__ ow, const float* __restrict__ obias,
          const float* __restrict__ l1s, const float* __restrict__ l1b,
          const float* __restrict__ f1w, const float* __restrict__ f1b,
          const float* __restrict__ f2w, const float* __restrict__ f2b,
          const float* __restrict__ l2s, const float* __restrict__ l2b,
          const float* __restrict__ hls, const float* __restrict__ hlb,
          const float* __restrict__ h1w, const float* __restrict__ h1b,
          const float* __restrict__ h2w, const float* __restrict__ h2b,
          float* __restrict__ out)
{
  extern __shared__ float sm[];
  float* h    = sm + OFF_H;     // [64][128]
  float* qkv  = sm + OFF_QKV;   // [192][128]: q 0..63, k 64..127, v 128..191
  float* att  = sm + OFF_ATT;   // [sk][sq] stride 130; also ff hidden / out-proj tmp / scratch

  const int tid = threadIdx.x;
  const int b   = blockIdx.x;

  // ---------------- Phase A: gather + input projection ----------------
  {
    const int s = tid & 127, half = tid >> 7;
    int qi = __ldg(q_lin_idx + b);
    int i  = qi >> 13;            // / (NY*NT) = /8192
    int rr = qi & 8191;
    int j  = rr >> 6;             // / NT
    int kk = rr & 63;
    int di = __ldg(offs + 3*s), dj = __ldg(offs + 3*s + 1), dk = __ldg(offs + 3*s + 2);
    int I = (i + di) & (NX_-1);
    int J = (j + dj) & (NY_-1);
    int T = min(max(kk + dk, 0), NT_-1);
    int nb = (I << 13) + (J << 6) + T;
    float qx = __ldg(coords + 3*qi), qy = __ldg(coords + 3*qi + 1), qt = __ldg(coords + 3*qi + 2);
    float nx = __ldg(coords + 3*nb), ny = __ldg(coords + 3*nb + 1), nt = __ldg(coords + 3*nb + 2);
    float g0 = expf(__ldg(lg+0)), g1 = expf(__ldg(lg+1)), g2 = expf(__ldg(lg+2));
    float f0 = dper(nx - qx, 2.0f) * g0;
    float f1 = dper(ny - qy, 2.0f) * g1;
    float f2 = (nt - qt) * g2;
    float f3 = __ldg(vals + 3*nb), f4 = __ldg(vals + 3*nb + 1), f5 = __ldg(vals + 3*nb + 2);
    for (int d = half*32; d < half*32 + 32; d++){
      float a = __ldg(pb + d);
      a += __ldg(pw + 6*d + 0)*f0 + __ldg(pw + 6*d + 1)*f1 + __ldg(pw + 6*d + 2)*f2
         + __ldg(pw + 6*d + 3)*f3 + __ldg(pw + 6*d + 4)*f4 + __ldg(pw + 6*d + 5)*f5;
      h[d*128 + s] = a;
    }
  }
  __syncthreads();

  // ---------------- Phase B: 2 transformer layers ----------------
  for (int l = 0; l < 2; l++){
    // qkv projection
    gemm_tok<192,64,false>(h, qw + l*192*64, qbias + l*192, qkv, tid);
    __syncthreads();

    // attention, head by head
    for (int hd = 0; hd < 4; hd++){
      // scores: att[sk][sq] = 0.25 * sum_di q[di][sq]*k[di][sk]
      {
        const float* qb2 = qkv + (hd*16)*128;
        const float* kb  = qkv + (64 + hd*16)*128;
        const int tx = tid & 15, ty = tid >> 4;  // tx: sk tile of 8, ty: sq tile of 8
        ULL acc[8][4];
        ULL z = pk2(0.f, 0.f);
#pragma unroll
        for (int jj=0;jj<8;jj++)
#pragma unroll
          for (int p=0;p<4;p++) acc[jj][p] = z;
#pragma unroll 2
        for (int di=0; di<16; di++){
          ULL qp[4];
#pragma unroll
          for (int p=0;p<4;p++)
            qp[p] = *reinterpret_cast<const ULL*>(qb2 + di*128 + 8*ty + 2*p);
          float kv[8];
#pragma unroll
          for (int jj=0;jj<8;jj+=2){
            float2 k2 = *reinterpret_cast<const float2*>(kb + di*128 + 8*tx + jj);
            kv[jj] = k2.x; kv[jj+1] = k2.y;
          }
#pragma unroll
          for (int jj=0;jj<8;jj++){
            ULL kd = pk2(kv[jj], kv[jj]);
#pragma unroll
            for (int p=0;p<4;p++) FMA2(acc[jj][p], qp[p], kd, acc[jj][p]);
          }
        }
        ULL sc = pk2(0.25f, 0.25f);
#pragma unroll
        for (int jj=0;jj<8;jj++)
#pragma unroll
          for (int p=0;p<4;p++){
            ULL v; MUL2(v, acc[jj][p], sc);
            *reinterpret_cast<ULL*>(att + (8*tx+jj)*130 + 8*ty + 2*p) = v;
          }
      }
      __syncthreads();

      // softmax over sk for each sq row (warp per row)
      {
        const int w = tid >> 5, ln = tid & 31;
        for (int m = 0; m < 16; m++){
          int r = 8*m + w;
          float v[4];
#pragma unroll
          for (int u=0;u<4;u++) v[u] = att[(ln + 32*u)*130 + r];
          float mx = fmaxf(fmaxf(v[0],v[1]), fmaxf(v[2],v[3]));
#pragma unroll
          for (int off=16; off; off>>=1) mx = fmaxf(mx, __shfl_xor_sync(0xffffffffu, mx, off));
          float e[4]; float smv = 0.f;
#pragma unroll
          for (int u=0;u<4;u++){ e[u] = __expf(v[u]-mx); smv += e[u]; }
#pragma unroll
          for (int off=16; off; off>>=1) smv += __shfl_xor_sync(0xffffffffu, smv, off);
          float inv = 1.0f / smv;
#pragma unroll
          for (int u=0;u<4;u++) att[(ln + 32*u)*130 + r] = e[u]*inv;
        }
      }
      __syncthreads();

      // o[dv][sq] = sum_sk att[sk][sq] * v[dv][sk]  (write over q slice of this head)
      if (tid < 128){
        const int pg = tid & 15, dg = tid >> 4;  // pg: sq tile of 8, dg: dv pair
        float* obp      = qkv + (hd*16 + 2*dg)*128;
        const float* vb = qkv + (128 + hd*16 + 2*dg)*128;
        ULL a0[4], a1[4];
        ULL z = pk2(0.f,0.f);
#pragma unroll
        for (int p=0;p<4;p++){ a0[p]=z; a1[p]=z; }
#pragma unroll 4
        for (int sk=0; sk<128; sk++){
          float v0 = vb[sk], v1 = vb[128+sk];
          ULL vd0 = pk2(v0,v0), vd1 = pk2(v1,v1);
#pragma unroll
          for (int p=0;p<4;p++){
            ULL ap = *reinterpret_cast<const ULL*>(att + sk*130 + 8*pg + 2*p);
            FMA2(a0[p], ap, vd0, a0[p]);
            FMA2(a1[p], ap, vd1, a1[p]);
          }
        }
#pragma unroll
        for (int p=0;p<4;p++){
          *reinterpret_cast<ULL*>(obp + 8*pg + 2*p)       = a0[p];
          *reinterpret_cast<ULL*>(obp + 128 + 8*pg + 2*p) = a1[p];
        }
      }
      __syncthreads();
    }

    // output projection (reads o from q region), tmp into att region
    gemm_tok<64,64,false>(qkv, ow + l*64*64, obias + l*64, att, tid);
    __syncthreads();
    add_ln(h, att, l1s + l*64, l1b + l*64, tid);
    __syncthreads();

    // FF: hidden = relu(h @ ff1^T + b1) in att region; then ff2 into qkv region
    gemm_tok<128,64,true>(h, f1w + l*128*64, f1b + l*128, att, tid);
    __syncthreads();
    gemm_tok<64,128,false>(att, f2w + l*64*128, f2b + l*64, qkv, tid);
    __syncthreads();
    add_ln(h, qkv, l2s + l*64, l2b + l*64, tid);
    __syncthreads();
  }

  // ---------------- Phase C: mean pool + head MLP ----------------
  float* scr = att;
  {
    const int d = tid & 63, qt = tid >> 6;   // 4 quarters of 32 tokens
    float s0 = 0.f;
    for (int s2 = qt*32; s2 < qt*32 + 32; s2++) s0 += h[d*128 + s2];
    scr[qt*64 + d] = s0;
  }
  __syncthreads();
  if (tid < 64){
    float hm = (scr[tid] + scr[64+tid] + scr[128+tid] + scr[192+tid]) * (1.0f/128.0f);
    scr[256 + tid] = hm;
  }
  __syncthreads();
  if (tid < 32){
    float a = scr[256 + tid], c = scr[256 + 32 + tid];
    float sum = a + c, sq = a*a + c*c;
#pragma unroll
    for (int off=16; off; off>>=1){
      sum += __shfl_xor_sync(0xffffffffu, sum, off);
      sq  += __shfl_xor_sync(0xffffffffu, sq,  off);
    }
    if (tid == 0){
      float m = sum * (1.f/64.f);
      scr[320] = m;
      scr[321] = rsqrtf(sq * (1.f/64.f) - m*m + EPS_);
    }
  }
  __syncthreads();
  if (tid < 64){
    float m = scr[320], inv = scr[321];
    scr[384 + tid] = (scr[256+tid] - m)*inv*__ldg(hls+tid) + __ldg(hlb+tid);
  }
  __syncthreads();
  if (tid < 64){
    float acc = __ldg(h1b + tid);
    for (int k=0;k<64;k++) acc += scr[384+k]*__ldg(h1w + tid*64 + k);
    scr[448 + tid] = 0.5f*acc*(1.0f + erff(acc*0.70710678118654752f));
  }
  __syncthreads();
  if (tid < 3){
    float acc = __ldg(h2b + tid);
    for (int k=0;k<64;k++) acc += scr[448+k]*__ldg(h2w + tid*64 + k);
    out[b*3 + tid] = acc;
  }
}

extern "C" void kernel_launch(void* const* d_in, const int* in_sizes, int n_in,
                              void* d_out, int out_size)
{
  const int*   qli    = (const int*)  d_in[0];
  const int*   offs   = (const int*)  d_in[1];
  const float* coords = (const float*)d_in[2];
  const float* vals   = (const float*)d_in[3];
  const float* lg     = (const float*)d_in[4];
  const float* pw     = (const float*)d_in[5];
  const float* pb     = (const float*)d_in[6];
  const float* qw     = (const float*)d_in[7];
  const float* qb     = (const float*)d_in[8];
  const float* ow     = (const float*)d_in[9];
  const float* ob     = (const float*)d_in[10];
  const float* l1s    = (const float*)d_in[11];
  const float* l1b    = (const float*)d_in[12];
  const float* f1w    = (const float*)d_in[13];
  const float* f1b    = (const float*)d_in[14];
  const float* f2w    = (const float*)d_in[15];
  const float* f2b    = (const float*)d_in[16];
  const float* l2s    = (const float*)d_in[17];
  const float* l2b    = (const float*)d_in[18];
  const float* hls    = (const float*)d_in[19];
  const float* hlb    = (const float*)d_in[20];
  const float* h1w    = (const float*)d_in[21];
  const float* h1b    = (const float*)d_in[22];
  const float* h2w    = (const float*)d_in[23];
  const float* h2b    = (const float*)d_in[24];
  float* out = (float*)d_out;
  const int B = in_sizes[0];

  cudaFuncSetAttribute(ff_kernel, cudaFuncAttributeMaxDynamicSharedMemorySize,
                       SMEM_FLOATS * (int)sizeof(float));
  ff_kernel<<<B, 256, SMEM_FLOATS * sizeof(float)>>>(
      qli, offs, coords, vals, lg, pw, pb, qw, qb, ow, ob,
      l1s, l1b, f1w, f1b, f2w, f2b, l2s, l2b,
      hls, hlb, h1w, h1b, h2w, h2b, out);
}